// round 1
// baseline (speedup 1.0000x reference)
#include <cuda_runtime.h>
#include <cstdint>

// Problem constants (fixed by the dataset)
#define NN 100000
#define EE 1200000
// D = 64, hidden = 128

// Scratch: aggregated messages per node [N, 64]  (25.6 MB device global, no alloc)
__device__ float g_agg[NN * 64];

// ---------------------------------------------------------------------------
// Kernel 0: zero the aggregation buffer (float4 stores)
// ---------------------------------------------------------------------------
__global__ void zero_agg_kernel(int n4) {
    int i = blockIdx.x * blockDim.x + threadIdx.x;
    if (i < n4) {
        ((float4*)g_agg)[i] = make_float4(0.f, 0.f, 0.f, 0.f);
    }
}

// ---------------------------------------------------------------------------
// Kernel 1: scatter-add  agg[dst] += node_feat[src] + edge_feat[e]
// One thread per (edge, float4-chunk): 16 chunks of 4 floats per edge.
// Consecutive threads share the same edge -> edge_index loads broadcast,
// edge_feat loads fully coalesced. Vector atomic (red.global.add.v4.f32)
// quarters the L2 atomic op count vs scalar atomicAdd.
// ---------------------------------------------------------------------------
__global__ void scatter_kernel(const float* __restrict__ node_feat,
                               const float* __restrict__ edge_feat,
                               const int* __restrict__ ei, int E) {
    int gid = blockIdx.x * blockDim.x + threadIdx.x;
    if (gid >= E * 16) return;
    int e = gid >> 4;
    int c = gid & 15;
    int s = __ldg(ei + e);
    int d = __ldg(ei + E + e);
    float4 nf = __ldg(((const float4*)node_feat) + s * 16 + c);
    float4 ef = __ldg(((const float4*)edge_feat) + (size_t)e * 16 + c);
    float4 m = make_float4(nf.x + ef.x, nf.y + ef.y, nf.z + ef.z, nf.w + ef.w);
    float* p = g_agg + (size_t)d * 64 + (c << 2);
    asm volatile("red.global.add.v4.f32 [%0], {%1, %2, %3, %4};"
                 :: "l"(p), "f"(m.x), "f"(m.y), "f"(m.z), "f"(m.w)
                 : "memory");
}

// ---------------------------------------------------------------------------
// Kernel 2: fused 2-layer MLP  out = relu(agg @ W1 + b1) @ W2 + b2
// One thread per node. h and o accumulators live in registers (inner j loops
// fully unrolled -> static indexing). Layer-2 needs h[k2] with dynamic k2, so
// h round-trips through padded shared memory (bank = (tid + k2) % 32,
// conflict-free). Weights (64 KB) are uniform-address LDG.128 -> L1 broadcast.
// ---------------------------------------------------------------------------
__global__ void __launch_bounds__(128) mlp_kernel(
    const float* __restrict__ W1, const float* __restrict__ b1,
    const float* __restrict__ W2, const float* __restrict__ b2,
    float* __restrict__ out, int N) {
    __shared__ float sh[128 * 65];
    int n = blockIdx.x * 128 + threadIdx.x;
    if (n >= N) return;
    float* hrow = sh + threadIdx.x * 65;
    const float4* arow = (const float4*)(g_agg + (size_t)n * 64);

    float o[64];
#pragma unroll
    for (int j4 = 0; j4 < 16; j4++) {
        float4 b = __ldg(((const float4*)b2) + j4);
        o[4 * j4 + 0] = b.x; o[4 * j4 + 1] = b.y;
        o[4 * j4 + 2] = b.z; o[4 * j4 + 3] = b.w;
    }

#pragma unroll 1
    for (int half = 0; half < 2; half++) {
        float h[64];
#pragma unroll
        for (int j4 = 0; j4 < 16; j4++) {
            float4 b = __ldg(((const float4*)(b1 + half * 64)) + j4);
            h[4 * j4 + 0] = b.x; h[4 * j4 + 1] = b.y;
            h[4 * j4 + 2] = b.z; h[4 * j4 + 3] = b.w;
        }
        // Layer 1 accumulation: h[j] += a_k * W1[k][half*64 + j]
#pragma unroll 1
        for (int kk = 0; kk < 16; kk++) {
            float4 a = __ldg(arow + kk);
#pragma unroll
            for (int q = 0; q < 4; q++) {
                float aq = (q == 0) ? a.x : (q == 1) ? a.y : (q == 2) ? a.z : a.w;
                const float4* w = (const float4*)(W1 + (kk * 4 + q) * 128 + half * 64);
#pragma unroll
                for (int j4 = 0; j4 < 16; j4++) {
                    float4 wv = __ldg(w + j4);
                    h[4 * j4 + 0] += aq * wv.x;
                    h[4 * j4 + 1] += aq * wv.y;
                    h[4 * j4 + 2] += aq * wv.z;
                    h[4 * j4 + 3] += aq * wv.w;
                }
            }
        }
        // ReLU -> padded shared (so layer 2 can index dynamically)
#pragma unroll
        for (int j = 0; j < 64; j++) hrow[j] = fmaxf(h[j], 0.0f);

        // Layer 2 accumulation: o[j] += h[k2] * W2[half*64 + k2][j]
#pragma unroll 1
        for (int k2 = 0; k2 < 64; k2++) {
            float hk = hrow[k2];
            const float4* w = (const float4*)(W2 + (half * 64 + k2) * 64);
#pragma unroll
            for (int j4 = 0; j4 < 16; j4++) {
                float4 wv = __ldg(w + j4);
                o[4 * j4 + 0] += hk * wv.x;
                o[4 * j4 + 1] += hk * wv.y;
                o[4 * j4 + 2] += hk * wv.z;
                o[4 * j4 + 3] += hk * wv.w;
            }
        }
    }

    float4* orow = (float4*)(out + (size_t)n * 64);
#pragma unroll
    for (int j4 = 0; j4 < 16; j4++)
        orow[j4] = make_float4(o[4 * j4], o[4 * j4 + 1], o[4 * j4 + 2], o[4 * j4 + 3]);
}

// ---------------------------------------------------------------------------
// Launch: zero -> scatter -> fused MLP   (all on legacy stream, capturable)
// ---------------------------------------------------------------------------
extern "C" void kernel_launch(void* const* d_in, const int* in_sizes, int n_in,
                              void* d_out, int out_size) {
    const float* node_feat = (const float*)d_in[0];
    const float* edge_feat = (const float*)d_in[1];
    const int*   ei        = (const int*)d_in[2];
    const float* W1        = (const float*)d_in[3];
    const float* b1        = (const float*)d_in[4];
    const float* W2        = (const float*)d_in[5];
    const float* b2        = (const float*)d_in[6];
    float* out = (float*)d_out;

    int N = in_sizes[0] / 64;   // 100000
    int E = in_sizes[2] / 2;    // 1200000

    int n4 = N * 16;            // float4 count of agg
    zero_agg_kernel<<<(n4 + 255) / 256, 256>>>(n4);
    scatter_kernel<<<(E * 16 + 255) / 256, 256>>>(node_feat, edge_feat, ei, E);
    mlp_kernel<<<(N + 127) / 128, 128>>>(W1, b1, W2, b2, out, N);
}

// round 2
// speedup vs baseline: 2.3415x; 2.3415x over previous
#include <cuda_runtime.h>
#include <cstdint>

#define NN 100000
#define EE 1200000

// Scratch: aggregated messages per node [N, 64]
__device__ float g_agg[NN * 64];

// ---------------------------------------------------------------------------
// Kernel 0: zero the aggregation buffer
// ---------------------------------------------------------------------------
__global__ void zero_agg_kernel(int n4) {
    int i = blockIdx.x * blockDim.x + threadIdx.x;
    if (i < n4) ((float4*)g_agg)[i] = make_float4(0.f, 0.f, 0.f, 0.f);
}

// ---------------------------------------------------------------------------
// Kernel 1: scatter-add  agg[dst] += node_feat[src] + edge_feat[e]
// (unchanged from round 1 for attribution)
// ---------------------------------------------------------------------------
__global__ void scatter_kernel(const float* __restrict__ node_feat,
                               const float* __restrict__ edge_feat,
                               const int* __restrict__ ei, int E) {
    int gid = blockIdx.x * blockDim.x + threadIdx.x;
    if (gid >= E * 16) return;
    int e = gid >> 4;
    int c = gid & 15;
    int s = __ldg(ei + e);
    int d = __ldg(ei + E + e);
    float4 nf = __ldg(((const float4*)node_feat) + s * 16 + c);
    float4 ef = __ldg(((const float4*)edge_feat) + (size_t)e * 16 + c);
    float4 m = make_float4(nf.x + ef.x, nf.y + ef.y, nf.z + ef.z, nf.w + ef.w);
    float* p = g_agg + (size_t)d * 64 + (c << 2);
    asm volatile("red.global.add.v4.f32 [%0], {%1, %2, %3, %4};"
                 :: "l"(p), "f"(m.x), "f"(m.y), "f"(m.z), "f"(m.w)
                 : "memory");
}

// ---------------------------------------------------------------------------
// Packed f32x2 helpers (Blackwell FFMA2 — PTX only)
// ---------------------------------------------------------------------------
__device__ __forceinline__ unsigned long long fma2(unsigned long long a,
                                                   unsigned long long b,
                                                   unsigned long long c) {
    unsigned long long d;
    asm("fma.rn.f32x2 %0, %1, %2, %3;" : "=l"(d) : "l"(a), "l"(b), "l"(c));
    return d;
}
__device__ __forceinline__ unsigned long long pack2(float x, float y) {
    unsigned long long d;
    asm("mov.b64 %0, {%1, %2};" : "=l"(d) : "f"(x), "f"(y));
    return d;
}
__device__ __forceinline__ void unpack2(unsigned long long v, float& x, float& y) {
    asm("mov.b64 {%0, %1}, %2;" : "=f"(x), "=f"(y) : "l"(v));
}

// ---------------------------------------------------------------------------
// Kernel 2: fused 2-layer MLP as smem-staged register-tiled GEMM.
// Block: 64 nodes x 256 threads. All GEMM operands from shared memory.
// GEMM1: thread tile 4m x 8j (4 f32x2 pairs); GEMM2: 4m x 4j (2 pairs).
// ---------------------------------------------------------------------------
#define BM 64
#define MLP_THREADS 256
#define AT_STRIDE 68   // [64][68] transposed agg tile (16B-aligned rows)
#define HS_STRIDE 68   // [128][68] hidden tile, stored H[j][m]
#define SM_AT 0
#define SM_W1 (SM_AT + 64 * AT_STRIDE)          // [64][128]
#define SM_HS (SM_W1 + 64 * 128)                // [128][68]
#define SM_W2 (SM_HS + 128 * HS_STRIDE)         // [128][64]
#define SM_FLOATS (SM_W2 + 128 * 64)
#define SMEM_BYTES (SM_FLOATS * 4)

__global__ void __launch_bounds__(MLP_THREADS) mlp_kernel(
    const float* __restrict__ W1, const float* __restrict__ b1,
    const float* __restrict__ W2, const float* __restrict__ b2,
    float* __restrict__ out, int N) {
    extern __shared__ float sm[];
    float* aT  = sm + SM_AT;
    float* W1s = sm + SM_W1;
    float* Hs  = sm + SM_HS;
    float* W2s = sm + SM_W2;
    int tid = threadIdx.x;
    int node0 = blockIdx.x * BM;

    // Stage W1 [64][128] and W2 [128][64] (contiguous copies, 8 float4 each)
#pragma unroll
    for (int i = 0; i < 8; i++) {
        int f = tid + i * 256;
        ((float4*)W1s)[f] = __ldg(((const float4*)W1) + f);
    }
#pragma unroll
    for (int i = 0; i < 8; i++) {
        int f = tid + i * 256;
        ((float4*)W2s)[f] = __ldg(((const float4*)W2) + f);
    }
    // Stage agg tile transposed: aT[k][m] = agg[node0+m][k]
#pragma unroll
    for (int i = 0; i < 4; i++) {
        int f = tid + i * 256;          // float4 id, 0..1023
        int r = f >> 4;                 // node within tile 0..63
        int c4 = f & 15;                // float4 column
        int n = node0 + r;
        float4 v = (n < N) ? __ldg(((const float4*)g_agg) + (size_t)n * 16 + c4)
                           : make_float4(0.f, 0.f, 0.f, 0.f);
        int c = c4 * 4;
        aT[(c + 0) * AT_STRIDE + r] = v.x;
        aT[(c + 1) * AT_STRIDE + r] = v.y;
        aT[(c + 2) * AT_STRIDE + r] = v.z;
        aT[(c + 3) * AT_STRIDE + r] = v.w;
    }
    __syncthreads();

    int m0 = (tid & 15) * 4;        // 16 m-groups of 4
    int j0 = (tid >> 4) * 8;        // 16 j-groups of 8 (GEMM1)

    // ---------------- GEMM1: H = relu(A @ W1 + b1) ----------------
    unsigned long long acc[4][4];
    {
        float4 blo = __ldg((const float4*)(b1 + j0));
        float4 bhi = __ldg((const float4*)(b1 + j0 + 4));
        unsigned long long bj[4] = { pack2(blo.x, blo.y), pack2(blo.z, blo.w),
                                     pack2(bhi.x, bhi.y), pack2(bhi.z, bhi.w) };
#pragma unroll
        for (int m = 0; m < 4; m++)
#pragma unroll
            for (int p = 0; p < 4; p++) acc[m][p] = bj[p];
    }
#pragma unroll 4
    for (int k = 0; k < 64; k++) {
        float4 av = *(const float4*)(aT + k * AT_STRIDE + m0);
        const float4* wp = (const float4*)(W1s + k * 128 + j0);
        float4 w0 = wp[0], w1 = wp[1];
        unsigned long long wv[4] = { pack2(w0.x, w0.y), pack2(w0.z, w0.w),
                                     pack2(w1.x, w1.y), pack2(w1.z, w1.w) };
        unsigned long long am[4] = { pack2(av.x, av.x), pack2(av.y, av.y),
                                     pack2(av.z, av.z), pack2(av.w, av.w) };
#pragma unroll
        for (int m = 0; m < 4; m++)
#pragma unroll
            for (int p = 0; p < 4; p++)
                acc[m][p] = fma2(am[m], wv[p], acc[m][p]);
    }
    // ReLU and store transposed: Hs[j][m]
#pragma unroll
    for (int m = 0; m < 4; m++)
#pragma unroll
        for (int p = 0; p < 4; p++) {
            float x, y; unpack2(acc[m][p], x, y);
            Hs[(j0 + 2 * p + 0) * HS_STRIDE + m0 + m] = fmaxf(x, 0.f);
            Hs[(j0 + 2 * p + 1) * HS_STRIDE + m0 + m] = fmaxf(y, 0.f);
        }
    __syncthreads();

    // ---------------- GEMM2: out = H @ W2 + b2 ----------------
    int j0b = (tid >> 4) * 4;       // 16 j-groups of 4
    unsigned long long acc2[4][2];
    {
        float4 bv = __ldg((const float4*)(b2 + j0b));
        unsigned long long bA = pack2(bv.x, bv.y), bB = pack2(bv.z, bv.w);
#pragma unroll
        for (int m = 0; m < 4; m++) { acc2[m][0] = bA; acc2[m][1] = bB; }
    }
#pragma unroll 4
    for (int k = 0; k < 128; k++) {
        float4 hv = *(const float4*)(Hs + k * HS_STRIDE + m0);
        float4 wv4 = *(const float4*)(W2s + k * 64 + j0b);
        unsigned long long wv[2] = { pack2(wv4.x, wv4.y), pack2(wv4.z, wv4.w) };
        unsigned long long hm[4] = { pack2(hv.x, hv.x), pack2(hv.y, hv.y),
                                     pack2(hv.z, hv.z), pack2(hv.w, hv.w) };
#pragma unroll
        for (int m = 0; m < 4; m++) {
            acc2[m][0] = fma2(hm[m], wv[0], acc2[m][0]);
            acc2[m][1] = fma2(hm[m], wv[1], acc2[m][1]);
        }
    }
#pragma unroll
    for (int m = 0; m < 4; m++) {
        int n = node0 + m0 + m;
        if (n < N) {
            float4 v;
            unpack2(acc2[m][0], v.x, v.y);
            unpack2(acc2[m][1], v.z, v.w);
            *(float4*)(out + (size_t)n * 64 + j0b) = v;
        }
    }
}

// ---------------------------------------------------------------------------
// Launch: zero -> scatter -> tiled MLP
// ---------------------------------------------------------------------------
extern "C" void kernel_launch(void* const* d_in, const int* in_sizes, int n_in,
                              void* d_out, int out_size) {
    const float* node_feat = (const float*)d_in[0];
    const float* edge_feat = (const float*)d_in[1];
    const int*   ei        = (const int*)d_in[2];
    const float* W1        = (const float*)d_in[3];
    const float* b1        = (const float*)d_in[4];
    const float* W2        = (const float*)d_in[5];
    const float* b2        = (const float*)d_in[6];
    float* out = (float*)d_out;

    int N = in_sizes[0] / 64;   // 100000
    int E = in_sizes[2] / 2;    // 1200000

    cudaFuncSetAttribute(mlp_kernel, cudaFuncAttributeMaxDynamicSharedMemorySize,
                         SMEM_BYTES);

    int n4 = N * 16;
    zero_agg_kernel<<<(n4 + 255) / 256, 256>>>(n4);
    scatter_kernel<<<(E * 16 + 255) / 256, 256>>>(node_feat, edge_feat, ei, E);
    mlp_kernel<<<(N + BM - 1) / BM, MLP_THREADS, SMEM_BYTES>>>(W1, b1, W2, b2, out, N);
}